// round 3
// baseline (speedup 1.0000x reference)
#include <cuda_runtime.h>
#include <cuda_bf16.h>
#include <cstdint>
#include <math.h>

#define NN 100000
#define EE 800000
#define NB_MAX 512

// ---------------- scratch (device globals; no cudaMalloc allowed) ----------------
__device__ int   g_cnt[NN];
__device__ int   g_row[NN + 1];
__device__ int   g_cur[NN];
__device__ int   g_bsum[NB_MAX];
__device__ int   g_csrc[EE];
__device__ float g_h [NN * 128];
__device__ float g_xl[NN * 128];
__device__ float g_xr[NN * 128];
__device__ float g_gg[NN * 128];
__device__ float g_w1cat[128 * 128];
__device__ float g_b1cat[128];

// ---------------- CSR build ----------------
__global__ void k_zero(int n) {
    int i = blockIdx.x * blockDim.x + threadIdx.x;
    if (i < n) g_cnt[i] = 0;
}

__global__ void k_count(const int* __restrict__ dstv, int e) {
    int i = blockIdx.x * blockDim.x + threadIdx.x;
    if (i < e) atomicAdd(&g_cnt[dstv[i]], 1);
}

__global__ void k_scan_a(int n) {
    __shared__ int sh[256];
    int i = blockIdx.x * 256 + threadIdx.x;
    int v = (i < n) ? g_cnt[i] : 0;
    sh[threadIdx.x] = v;
    __syncthreads();
    #pragma unroll
    for (int o = 1; o < 256; o <<= 1) {
        int t = (threadIdx.x >= o) ? sh[threadIdx.x - o] : 0;
        __syncthreads();
        sh[threadIdx.x] += t;
        __syncthreads();
    }
    if (i < n) g_row[i] = sh[threadIdx.x] - v;           // exclusive within block
    if (threadIdx.x == 255) g_bsum[blockIdx.x] = sh[255];
}

__global__ void k_scan_b(int nb) {
    __shared__ int sh[NB_MAX];
    int t = threadIdx.x;
    int v = (t < nb) ? g_bsum[t] : 0;
    sh[t] = v;
    __syncthreads();
    #pragma unroll
    for (int o = 1; o < NB_MAX; o <<= 1) {
        int u = (t >= o) ? sh[t - o] : 0;
        __syncthreads();
        sh[t] += u;
        __syncthreads();
    }
    if (t < nb) g_bsum[t] = sh[t] - v;                   // exclusive block offsets
}

__global__ void k_scan_c(int n, int e) {
    int i = blockIdx.x * 256 + threadIdx.x;
    if (i < n) {
        int r = g_row[i] + g_bsum[blockIdx.x];
        g_row[i] = r;
        g_cur[i] = r;
    }
    if (i == 0) g_row[n] = e;
}

__global__ void k_scatter(const int* __restrict__ srcv, const int* __restrict__ dstv, int e) {
    int i = blockIdx.x * blockDim.x + threadIdx.x;
    if (i < e) {
        int pos = atomicAdd(&g_cur[dstv[i]], 1);
        g_csrc[pos] = srcv[i];
    }
}

// Sort each node's adjacency list by src value -> deterministic summation order.
__global__ void k_sortcsr(int n) {
    int i = blockIdx.x * blockDim.x + threadIdx.x;
    if (i >= n) return;
    int b = g_row[i], e2 = g_row[i + 1];
    for (int a = b + 1; a < e2; a++) {
        int v = g_csrc[a];
        int k = a;
        while (k > b && g_csrc[k - 1] > v) { g_csrc[k] = g_csrc[k - 1]; k--; }
        g_csrc[k] = v;
    }
}

// ---------------- LayerNorm kernels ----------------
__global__ void __launch_bounds__(256) k_ln64(const float* __restrict__ x,
                                              const float* __restrict__ g,
                                              const float* __restrict__ b,
                                              float* __restrict__ out, int n) {
    int w = (blockIdx.x * 256 + threadIdx.x) >> 5;
    int lane = threadIdx.x & 31;
    if (w >= n) return;
    float2 v = *(const float2*)(x + (size_t)w * 64 + lane * 2);
    float s = v.x + v.y;
    float q = v.x * v.x + v.y * v.y;
    #pragma unroll
    for (int o = 16; o; o >>= 1) {
        s += __shfl_xor_sync(0xffffffffu, s, o);
        q += __shfl_xor_sync(0xffffffffu, q, o);
    }
    float m  = s * (1.f / 64.f);
    float var = q * (1.f / 64.f) - m * m;
    float rs = rsqrtf(var + 1e-5f);
    float2 gg = *(const float2*)(g + lane * 2);
    float2 bb = *(const float2*)(b + lane * 2);
    float2 o2;
    o2.x = (v.x - m) * rs * gg.x + bb.x;
    o2.y = (v.y - m) * rs * gg.y + bb.y;
    *(float2*)(out + (size_t)w * 64 + lane * 2) = o2;
}

__global__ void __launch_bounds__(256) k_ln128(const float* __restrict__ in,
                                               const float* __restrict__ g,
                                               const float* __restrict__ b,
                                               const float* __restrict__ res,
                                               float rscale, int doRelu,
                                               float* __restrict__ out, int n) {
    int w = (blockIdx.x * 256 + threadIdx.x) >> 5;
    int lane = threadIdx.x & 31;
    if (w >= n) return;
    int c0 = lane * 4;
    float4 v = *(const float4*)(in + (size_t)w * 128 + c0);
    float s = v.x + v.y + v.z + v.w;
    float q = v.x * v.x + v.y * v.y + v.z * v.z + v.w * v.w;
    #pragma unroll
    for (int o = 16; o; o >>= 1) {
        s += __shfl_xor_sync(0xffffffffu, s, o);
        q += __shfl_xor_sync(0xffffffffu, q, o);
    }
    float m   = s * (1.f / 128.f);
    float var = q * (1.f / 128.f) - m * m;
    float rs  = rsqrtf(var + 1e-5f);
    float4 gg = *(const float4*)(g + c0);
    float4 bb = *(const float4*)(b + c0);
    float4 y;
    y.x = (v.x - m) * rs * gg.x + bb.x;
    y.y = (v.y - m) * rs * gg.y + bb.y;
    y.z = (v.z - m) * rs * gg.z + bb.z;
    y.w = (v.w - m) * rs * gg.w + bb.w;
    if (res) {
        float4 r4 = *(const float4*)(res + (size_t)w * 128 + c0);
        y.x += rscale * r4.x; y.y += rscale * r4.y;
        y.z += rscale * r4.z; y.w += rscale * r4.w;
    }
    if (doRelu) {
        y.x = fmaxf(y.x, 0.f); y.y = fmaxf(y.y, 0.f);
        y.z = fmaxf(y.z, 0.f); y.w = fmaxf(y.w, 0.f);
    }
    *(float4*)(out + (size_t)w * 128 + c0) = y;
}

// ---------------- tensor-core GEMM (bf16x3 split, fp32-equivalent) ----------------
// C[n,128] = A[n,K] * W[K,128] (+bias, relu).  A,W,C fp32 in gmem; bf16 hi/lo in smem.

__device__ __forceinline__ void ldsm4(uint32_t addr, uint32_t& r0, uint32_t& r1,
                                      uint32_t& r2, uint32_t& r3) {
    asm volatile("ldmatrix.sync.aligned.m8n8.x4.shared.b16 {%0,%1,%2,%3}, [%4];"
                 : "=r"(r0), "=r"(r1), "=r"(r2), "=r"(r3) : "r"(addr));
}
__device__ __forceinline__ void ldsm4t(uint32_t addr, uint32_t& r0, uint32_t& r1,
                                       uint32_t& r2, uint32_t& r3) {
    asm volatile("ldmatrix.sync.aligned.m8n8.x4.trans.shared.b16 {%0,%1,%2,%3}, [%4];"
                 : "=r"(r0), "=r"(r1), "=r"(r2), "=r"(r3) : "r"(addr));
}
__device__ __forceinline__ void mma_bf16(float* c, const uint32_t* a, const uint32_t* b) {
    asm volatile(
        "mma.sync.aligned.m16n8k16.row.col.f32.bf16.bf16.f32 "
        "{%0,%1,%2,%3},{%4,%5,%6,%7},{%8,%9},{%0,%1,%2,%3};"
        : "+f"(c[0]), "+f"(c[1]), "+f"(c[2]), "+f"(c[3])
        : "r"(a[0]), "r"(a[1]), "r"(a[2]), "r"(a[3]), "r"(b[0]), "r"(b[1]));
}

__device__ __forceinline__ void split4(float4 v, uint2& hi, uint2& lo) {
    __nv_bfloat16 h0 = __float2bfloat16(v.x), h1 = __float2bfloat16(v.y);
    __nv_bfloat16 h2 = __float2bfloat16(v.z), h3 = __float2bfloat16(v.w);
    __nv_bfloat16 l0 = __float2bfloat16(v.x - __bfloat162float(h0));
    __nv_bfloat16 l1 = __float2bfloat16(v.y - __bfloat162float(h1));
    __nv_bfloat16 l2 = __float2bfloat16(v.z - __bfloat162float(h2));
    __nv_bfloat16 l3 = __float2bfloat16(v.w - __bfloat162float(h3));
    hi.x = ((uint32_t)__bfloat16_as_ushort(h1) << 16) | __bfloat16_as_ushort(h0);
    hi.y = ((uint32_t)__bfloat16_as_ushort(h3) << 16) | __bfloat16_as_ushort(h2);
    lo.x = ((uint32_t)__bfloat16_as_ushort(l1) << 16) | __bfloat16_as_ushort(l0);
    lo.y = ((uint32_t)__bfloat16_as_ushort(l3) << 16) | __bfloat16_as_ushort(l2);
}

#define SA 40    // smem row stride (bf16 elems) for A tile (128 x 32)
#define SW 136   // smem row stride (bf16 elems) for W tile (32 x 128)

template <int K>
__global__ void __launch_bounds__(256, 1) k_gemm_tc(const float* __restrict__ A,
                                                    const float* __restrict__ W,
                                                    float* __restrict__ C, int n,
                                                    const float* __restrict__ bias,
                                                    int doRelu) {
    __shared__ __nv_bfloat16 As_hi[128 * SA];
    __shared__ __nv_bfloat16 As_lo[128 * SA];
    __shared__ __nv_bfloat16 Ws_hi[32 * SW];
    __shared__ __nv_bfloat16 Ws_lo[32 * SW];

    const int tid   = threadIdx.x;
    const int lane  = tid & 31;
    const int wid   = tid >> 5;
    const int warpM = wid & 3;    // 4 warps along M (32 rows each)
    const int warpN = wid >> 2;   // 2 warps along N (64 cols each)
    const int row0  = blockIdx.x * 128;

    float acc[2][8][4];
    #pragma unroll
    for (int i = 0; i < 2; i++)
        #pragma unroll
        for (int j = 0; j < 8; j++)
            #pragma unroll
            for (int k = 0; k < 4; k++) acc[i][j][k] = 0.f;

    const uint32_t sAhi = (uint32_t)__cvta_generic_to_shared(As_hi);
    const uint32_t sAlo = (uint32_t)__cvta_generic_to_shared(As_lo);
    const uint32_t sWhi = (uint32_t)__cvta_generic_to_shared(Ws_hi);
    const uint32_t sWlo = (uint32_t)__cvta_generic_to_shared(Ws_lo);

    for (int k0 = 0; k0 < K; k0 += 32) {
        __syncthreads();
        // ---- stage A chunk [128 x 32] fp32 -> bf16 hi/lo in smem ----
        {
            const int col = (tid & 7) * 4;
            const int rr  = tid >> 3;  // 0..31
            #pragma unroll
            for (int p = 0; p < 4; p++) {
                int row  = rr + p * 32;
                int grow = row0 + row;
                float4 v = make_float4(0.f, 0.f, 0.f, 0.f);
                if (grow < n) v = *(const float4*)(A + (size_t)grow * K + k0 + col);
                uint2 hi, lo;
                split4(v, hi, lo);
                *(uint2*)(As_hi + row * SA + col) = hi;
                *(uint2*)(As_lo + row * SA + col) = lo;
            }
        }
        // ---- stage W chunk [32 x 128] ----
        {
            const int col = (tid & 31) * 4;
            const int rr  = tid >> 5;  // 0..7
            #pragma unroll
            for (int p = 0; p < 4; p++) {
                int row  = rr + p * 8;
                float4 v = *(const float4*)(W + (size_t)(k0 + row) * 128 + col);
                uint2 hi, lo;
                split4(v, hi, lo);
                *(uint2*)(Ws_hi + row * SW + col) = hi;
                *(uint2*)(Ws_lo + row * SW + col) = lo;
            }
        }
        __syncthreads();
        // ---- 2 k16-steps per chunk ----
        #pragma unroll
        for (int ks = 0; ks < 2; ks++) {
            uint32_t ah[2][4];
            uint32_t al[2][4];
            uint32_t bh[8][2];
            uint32_t bl[8][2];
            #pragma unroll
            for (int ma = 0; ma < 2; ma++) {
                int row  = warpM * 32 + ma * 16 + (lane & 15);
                int colk = ks * 16 + 8 * (lane >> 4);
                uint32_t off = (uint32_t)(row * SA + colk) * 2u;
                ldsm4(sAhi + off, ah[ma][0], ah[ma][1], ah[ma][2], ah[ma][3]);
                ldsm4(sAlo + off, al[ma][0], al[ma][1], al[ma][2], al[ma][3]);
            }
            #pragma unroll
            for (int nb = 0; nb < 4; nb++) {
                int kr = ks * 16 + (lane & 15);
                int nc = warpN * 64 + nb * 16 + 8 * (lane >> 4);
                uint32_t off = (uint32_t)(kr * SW + nc) * 2u;
                uint32_t r0, r1, r2, r3;
                ldsm4t(sWhi + off, r0, r1, r2, r3);
                bh[nb * 2][0] = r0; bh[nb * 2][1] = r1;
                bh[nb * 2 + 1][0] = r2; bh[nb * 2 + 1][1] = r3;
                ldsm4t(sWlo + off, r0, r1, r2, r3);
                bl[nb * 2][0] = r0; bl[nb * 2][1] = r1;
                bl[nb * 2 + 1][0] = r2; bl[nb * 2 + 1][1] = r3;
            }
            #pragma unroll
            for (int ma = 0; ma < 2; ma++)
                #pragma unroll
                for (int na = 0; na < 8; na++) {
                    mma_bf16(acc[ma][na], al[ma], bh[na]);
                    mma_bf16(acc[ma][na], ah[ma], bl[na]);
                    mma_bf16(acc[ma][na], ah[ma], bh[na]);
                }
        }
    }

    // ---- epilogue ----
    const int rbase = row0 + warpM * 32 + (lane >> 2);
    const int cbase = warpN * 64 + (lane & 3) * 2;
    #pragma unroll
    for (int na = 0; na < 8; na++) {
        int col = cbase + na * 8;
        float b0 = 0.f, b1 = 0.f;
        if (bias) { b0 = bias[col]; b1 = bias[col + 1]; }
        #pragma unroll
        for (int ma = 0; ma < 2; ma++) {
            #pragma unroll
            for (int h = 0; h < 2; h++) {
                int grow = rbase + ma * 16 + h * 8;
                if (grow < n) {
                    float2 o;
                    o.x = acc[ma][na][h * 2 + 0] + b0;
                    o.y = acc[ma][na][h * 2 + 1] + b1;
                    if (doRelu) { o.x = fmaxf(o.x, 0.f); o.y = fmaxf(o.y, 0.f); }
                    *(float2*)(C + (size_t)grow * 128 + col) = o;
                }
            }
        }
    }
}

// ---------------- GATv2 aggregation: warp per dst node, online softmax ----------------
// lane owns flat channels [4*lane, 4*lane+4); head of lane = lane/(32/H).
__global__ void __launch_bounds__(256) k_agg(const float* __restrict__ xl,
                                             const float* __restrict__ xr,
                                             const float* __restrict__ att,
                                             float* __restrict__ out, int n, int grp) {
    int w = (blockIdx.x * 256 + threadIdx.x) >> 5;
    int lane = threadIdx.x & 31;
    if (w >= n) return;
    int c0 = lane * 4;
    float4 a4 = *(const float4*)(att + c0);
    float4 r4 = *(const float4*)(xr + (size_t)w * 128 + c0);
    int beg = g_row[w], deg = g_row[w + 1] - beg;
    float m = -1e30f, s = 0.f;
    float4 acc = make_float4(0.f, 0.f, 0.f, 0.f);
    for (int j = -1; j < deg; j++) {       // j == -1 is the self-loop
        int sidx = (j < 0) ? w : g_csrc[beg + j];
        float4 x4 = *(const float4*)(xl + (size_t)sidx * 128 + c0);
        float e0 = x4.x + r4.x, e1 = x4.y + r4.y, e2 = x4.z + r4.z, e3 = x4.w + r4.w;
        e0 = (e0 > 0.f) ? e0 : 0.2f * e0;
        e1 = (e1 > 0.f) ? e1 : 0.2f * e1;
        e2 = (e2 > 0.f) ? e2 : 0.2f * e2;
        e3 = (e3 > 0.f) ? e3 : 0.2f * e3;
        float p = fmaf(a4.x, e0, fmaf(a4.y, e1, fmaf(a4.z, e2, a4.w * e3)));
        #pragma unroll
        for (int o = 1; o < 32; o <<= 1)
            if (o < grp) p += __shfl_xor_sync(0xffffffffu, p, o);
        float mn  = fmaxf(m, p);
        float sc  = __expf(m - mn);
        float wgt = __expf(p - mn);
        s = s * sc + wgt;
        acc.x = fmaf(acc.x, sc, wgt * x4.x);
        acc.y = fmaf(acc.y, sc, wgt * x4.y);
        acc.z = fmaf(acc.z, sc, wgt * x4.z);
        acc.w = fmaf(acc.w, sc, wgt * x4.w);
        m = mn;
    }
    float inv = 1.f / s;
    float4 o4 = make_float4(acc.x * inv, acc.y * inv, acc.z * inv, acc.w * inv);
    *(float4*)(out + (size_t)w * 128 + c0) = o4;
}

// ---------------- prediction heads ----------------
__global__ void k_w1cat(const float* __restrict__ w1a, const float* __restrict__ w1b,
                        const float* __restrict__ b1a, const float* __restrict__ b1b) {
    int i = blockIdx.x * blockDim.x + threadIdx.x;
    if (i < 128 * 64) {
        int r = i >> 6, c = i & 63;
        g_w1cat[r * 128 + c]      = w1a[i];
        g_w1cat[r * 128 + 64 + c] = w1b[i];
    }
    if (i < 64) { g_b1cat[i] = b1a[i]; g_b1cat[64 + i] = b1b[i]; }
}

__global__ void __launch_bounds__(256) k_head2(const float* __restrict__ T,
                                               const float* __restrict__ w2a,
                                               const float* __restrict__ b2a,
                                               const float* __restrict__ w2b,
                                               const float* __restrict__ b2b,
                                               float* __restrict__ out, int n) {
    int w = (blockIdx.x * 256 + threadIdx.x) >> 5;
    int lane = threadIdx.x & 31;
    if (w >= n) return;
    const float* t = T + (size_t)w * 128;
    float tA = fmaf(t[lane],      w2a[lane],      t[32 + lane] * w2a[32 + lane]);
    float tB = fmaf(t[64 + lane], w2b[lane],      t[96 + lane] * w2b[32 + lane]);
    #pragma unroll
    for (int o = 16; o; o >>= 1) {
        tA += __shfl_xor_sync(0xffffffffu, tA, o);
        tB += __shfl_xor_sync(0xffffffffu, tB, o);
    }
    if (lane == 0) {
        out[(size_t)2 * w]     = tA + b2a[0];
        out[(size_t)2 * w + 1] = tB + b2b[0];
    }
}

// ---------------- launch ----------------
extern "C" void kernel_launch(void* const* d_in, const int* in_sizes, int n_in,
                              void* d_out, int out_size) {
    const float* x       = (const float*)d_in[0];
    const int*   ei      = (const int*)  d_in[1];
    const float* ln_in_g = (const float*)d_in[2];
    const float* ln_in_b = (const float*)d_in[3];
    const float* w_l1    = (const float*)d_in[4];
    const float* w_r1    = (const float*)d_in[5];
    const float* att1    = (const float*)d_in[6];
    const float* ln1_g   = (const float*)d_in[7];
    const float* ln1_b   = (const float*)d_in[8];
    const float* w_l2    = (const float*)d_in[9];
    const float* w_r2    = (const float*)d_in[10];
    const float* att2    = (const float*)d_in[11];
    const float* ln2_g   = (const float*)d_in[12];
    const float* ln2_b   = (const float*)d_in[13];
    const float* w_l3    = (const float*)d_in[14];
    const float* w_r3    = (const float*)d_in[15];
    const float* att3    = (const float*)d_in[16];
    const float* ln3_g   = (const float*)d_in[17];
    const float* ln3_b   = (const float*)d_in[18];
    const float* rtt_w1  = (const float*)d_in[19];
    const float* rtt_b1  = (const float*)d_in[20];
    const float* rtt_w2  = (const float*)d_in[21];
    const float* rtt_b2  = (const float*)d_in[22];
    const float* ret_w1  = (const float*)d_in[23];
    const float* ret_b1  = (const float*)d_in[24];
    const float* ret_w2  = (const float*)d_in[25];
    const float* ret_b2  = (const float*)d_in[26];

    const int n = in_sizes[0] / 64;
    const int e = in_sizes[1] / 2;
    const int* srcv = ei;
    const int* dstv = ei + e;

    float *p_h, *p_xl, *p_xr, *p_gg, *p_w1, *p_b1;
    cudaGetSymbolAddress((void**)&p_h,  g_h);
    cudaGetSymbolAddress((void**)&p_xl, g_xl);
    cudaGetSymbolAddress((void**)&p_xr, g_xr);
    cudaGetSymbolAddress((void**)&p_gg, g_gg);
    cudaGetSymbolAddress((void**)&p_w1, g_w1cat);
    cudaGetSymbolAddress((void**)&p_b1, g_b1cat);

    const int NBn = (n + 255) / 256;
    const int EB  = (e + 255) / 256;
    const int WB  = (n + 7) / 8;       // warp-per-node, 256-thread blocks
    const int GB  = (n + 127) / 128;   // tensor GEMM M-tiles

    // CSR build (shared by all three layers)
    k_zero   <<<NBn, 256>>>(n);
    k_count  <<<EB,  256>>>(dstv, e);
    k_scan_a <<<NBn, 256>>>(n);
    k_scan_b <<<1, NB_MAX>>>(NBn);
    k_scan_c <<<NBn, 256>>>(n, e);
    k_scatter<<<EB,  256>>>(srcv, dstv, e);
    k_sortcsr<<<NBn, 256>>>(n);
    k_w1cat  <<<32,  256>>>(rtt_w1, ret_w1, rtt_b1, ret_b1);

    // input LayerNorm: x -> g_gg as [n,64]
    k_ln64<<<WB, 256>>>(x, ln_in_g, ln_in_b, p_gg, n);

    // layer 0 (F_IN=64 -> 128, 4 heads, no residual)
    k_gemm_tc<64><<<GB, 256>>>(p_gg, w_l1, p_xl, n, nullptr, 0);
    k_gemm_tc<64><<<GB, 256>>>(p_gg, w_r1, p_xr, n, nullptr, 0);
    k_agg<<<WB, 256>>>(p_xl, p_xr, att1, p_gg, n, 8);
    k_ln128<<<WB, 256>>>(p_gg, ln1_g, ln1_b, nullptr, 0.f, 1, p_h, n);

    // layer 1 (128 -> 128, 4 heads, residual*0.1, relu)
    k_gemm_tc<128><<<GB, 256>>>(p_h, w_l2, p_xl, n, nullptr, 0);
    k_gemm_tc<128><<<GB, 256>>>(p_h, w_r2, p_xr, n, nullptr, 0);
    k_agg<<<WB, 256>>>(p_xl, p_xr, att2, p_gg, n, 8);
    k_ln128<<<WB, 256>>>(p_gg, ln2_g, ln2_b, p_h, 0.1f, 1, p_h, n);

    // layer 2 (128 -> 128, 1 head, residual*0.1, no relu)
    k_gemm_tc<128><<<GB, 256>>>(p_h, w_l3, p_xl, n, nullptr, 0);
    k_gemm_tc<128><<<GB, 256>>>(p_h, w_r3, p_xr, n, nullptr, 0);
    k_agg<<<WB, 256>>>(p_xl, p_xr, att3, p_gg, n, 32);
    k_ln128<<<WB, 256>>>(p_gg, ln3_g, ln3_b, p_h, 0.1f, 0, p_h, n);

    // prediction heads: T = relu(h @ [rtt_w1|ret_w1] + b) ; out = [T_a@w2a+b2a, T_b@w2b+b2b]
    k_gemm_tc<128><<<GB, 256>>>(p_h, p_w1, p_xl, n, p_b1, 1);
    k_head2<<<WB, 256>>>(p_xl, rtt_w2, rtt_b2, ret_w2, ret_b2, (float*)d_out, n);
}

// round 5
// speedup vs baseline: 1.6307x; 1.6307x over previous
#include <cuda_runtime.h>
#include <cuda_bf16.h>
#include <cstdint>
#include <math.h>

#define NN 100000
#define EE 800000
#define NB_MAX 512

// ---------------- scratch (device globals; no cudaMalloc allowed) ----------------
__device__ int   g_cnt[NN];
__device__ int   g_row[NN + 1];
__device__ int   g_cur[NN];
__device__ int   g_bsum[NB_MAX];
__device__ int   g_csrc[EE];
__device__ float g_h [NN * 128];
__device__ float g_xl[NN * 128];
__device__ float g_xr[NN * 128];
__device__ float g_gg[NN * 128];
__device__ float g_b1cat[128];
__device__ __nv_bfloat16 g_pk[NN * 256];       // activation pack: [hi(K) | lo(K)] per row
__device__ __nv_bfloat16 g_W0[192 * 256];      // layer0 weight image [3K x 256], K=64
__device__ __nv_bfloat16 g_W1[384 * 256];      // layer1
__device__ __nv_bfloat16 g_W2[384 * 256];      // layer2
__device__ __nv_bfloat16 g_WH[384 * 128];      // head

// ---------------- mma helpers ----------------
__device__ __forceinline__ void ldsm4(uint32_t addr, uint32_t& r0, uint32_t& r1,
                                      uint32_t& r2, uint32_t& r3) {
    asm volatile("ldmatrix.sync.aligned.m8n8.x4.shared.b16 {%0,%1,%2,%3}, [%4];"
                 : "=r"(r0), "=r"(r1), "=r"(r2), "=r"(r3) : "r"(addr));
}
__device__ __forceinline__ void ldsm4t(uint32_t addr, uint32_t& r0, uint32_t& r1,
                                       uint32_t& r2, uint32_t& r3) {
    asm volatile("ldmatrix.sync.aligned.m8n8.x4.trans.shared.b16 {%0,%1,%2,%3}, [%4];"
                 : "=r"(r0), "=r"(r1), "=r"(r2), "=r"(r3) : "r"(addr));
}
__device__ __forceinline__ void mma_bf16(float* c, const uint32_t* a, uint32_t b0, uint32_t b1) {
    asm volatile(
        "mma.sync.aligned.m16n8k16.row.col.f32.bf16.bf16.f32 "
        "{%0,%1,%2,%3},{%4,%5,%6,%7},{%8,%9},{%0,%1,%2,%3};"
        : "+f"(c[0]), "+f"(c[1]), "+f"(c[2]), "+f"(c[3])
        : "r"(a[0]), "r"(a[1]), "r"(a[2]), "r"(a[3]), "r"(b0), "r"(b1));
}
__device__ __forceinline__ void split4(float4 v, uint2& hi, uint2& lo) {
    __nv_bfloat16 h0 = __float2bfloat16(v.x), h1 = __float2bfloat16(v.y);
    __nv_bfloat16 h2 = __float2bfloat16(v.z), h3 = __float2bfloat16(v.w);
    __nv_bfloat16 l0 = __float2bfloat16(v.x - __bfloat162float(h0));
    __nv_bfloat16 l1 = __float2bfloat16(v.y - __bfloat162float(h1));
    __nv_bfloat16 l2 = __float2bfloat16(v.z - __bfloat162float(h2));
    __nv_bfloat16 l3 = __float2bfloat16(v.w - __bfloat162float(h3));
    hi.x = ((uint32_t)__bfloat16_as_ushort(h1) << 16) | __bfloat16_as_ushort(h0);
    hi.y = ((uint32_t)__bfloat16_as_ushort(h3) << 16) | __bfloat16_as_ushort(h2);
    lo.x = ((uint32_t)__bfloat16_as_ushort(l1) << 16) | __bfloat16_as_ushort(l0);
    lo.y = ((uint32_t)__bfloat16_as_ushort(l3) << 16) | __bfloat16_as_ushort(l2);
}

// ---------------- weight pre-convert: fp32 [K x H] pair -> bf16 image [3K x NT] ----------------
// rows [0,K)=hi, [K,2K)=lo, [2K,3K)=hi (again), cols = [Wl | Wr]
template <int K, int NT>
__global__ void k_convW(const float* __restrict__ Wl, const float* __restrict__ Wr,
                        __nv_bfloat16* __restrict__ img) {
    int idx = blockIdx.x * blockDim.x + threadIdx.x;
    if (idx >= 3 * K * NT) return;
    int r = idx / NT, col = idx % NT;
    int t = r / K, k = r % K;
    const int H = NT / 2;
    float v = (col < H) ? Wl[k * H + col] : Wr[k * H + col - H];
    __nv_bfloat16 hi = __float2bfloat16(v);
    img[idx] = (t == 1) ? __float2bfloat16(v - __bfloat162float(hi)) : hi;
}

__global__ void k_biascat(const float* __restrict__ b1a, const float* __restrict__ b1b) {
    int i = threadIdx.x;
    if (i < 64) { g_b1cat[i] = b1a[i]; g_b1cat[64 + i] = b1b[i]; }
}

// ---------------- HMMA GEMM: out[128 or 2x128] = Apack[n,2K](bf16 hi|lo) x Wimg[3K,NT] ----------------
#define APAD 72
template <int K, int NT, bool BIAS_RELU>
__global__ void __launch_bounds__(256, 1) k_gemm_mma(
    const __nv_bfloat16* __restrict__ Apack,
    const __nv_bfloat16* __restrict__ Wimg,
    float* __restrict__ out1, float* __restrict__ out2,
    const float* __restrict__ bias, int n)
{
    constexpr int C = 3 * K / 64;          // k-chunks (64 wide)
    constexpr int BPAD = NT + 8;
    constexpr int ABYTES = 128 * APAD * 2;
    constexpr int BBYTES = 64 * BPAD * 2;
    constexpr int STG = ABYTES + BBYTES;
    constexpr int K2 = 2 * K;
    extern __shared__ char sm[];
    const uint32_t sbase = (uint32_t)__cvta_generic_to_shared(sm);
    const int tid = threadIdx.x, lane = tid & 31, wid = tid >> 5;
    const int wm = wid & 3, wn = wid >> 2;     // 4 warps M (32 rows), 2 warps N (NT/2 cols)
    const int row0 = blockIdx.x * 128;

    auto loadChunk = [&](int c) {
        const int per = K / 64;
        const int t = c / per;
        const int within = c - t * per;
        const int a_off = (t == 2 ? K : 0) + within * 64;
        const int brow = c * 64;
        const uint32_t sA = sbase + (uint32_t)(c % 3) * STG;
        const uint32_t sB = sA + ABYTES;
        #pragma unroll
        for (int i = tid; i < 1024; i += 256) {                 // A: 128 x 64
            int r = i >> 3, cc = (i & 7) * 8;
            int grow = row0 + r; if (grow > n - 1) grow = n - 1;
            uint32_t dst = sA + (uint32_t)(r * APAD + cc) * 2;
            const __nv_bfloat16* src = Apack + (size_t)grow * K2 + a_off + cc;
            asm volatile("cp.async.ca.shared.global [%0], [%1], 16;" :: "r"(dst), "l"(src));
        }
        #pragma unroll
        for (int i = tid; i < 64 * NT / 8; i += 256) {          // B: 64 x NT
            int r = i / (NT / 8), cc = (i % (NT / 8)) * 8;
            uint32_t dst = sB + (uint32_t)(r * BPAD + cc) * 2;
            const __nv_bfloat16* src = Wimg + (size_t)(brow + r) * NT + cc;
            asm volatile("cp.async.ca.shared.global [%0], [%1], 16;" :: "r"(dst), "l"(src));
        }
        asm volatile("cp.async.commit_group;" ::: "memory");
    };

    float acc[2][NT / 16][4];
    #pragma unroll
    for (int i = 0; i < 2; i++)
        #pragma unroll
        for (int j = 0; j < NT / 16; j++)
            #pragma unroll
            for (int q = 0; q < 4; q++) acc[i][j][q] = 0.f;

    loadChunk(0);
    loadChunk(1);

    for (int c = 0; c < C; c++) {
        if (c < C - 1) asm volatile("cp.async.wait_group 1;" ::: "memory");
        else           asm volatile("cp.async.wait_group 0;" ::: "memory");
        __syncthreads();
        if (c + 2 < C) loadChunk(c + 2);
        const uint32_t sA = sbase + (uint32_t)(c % 3) * STG;
        const uint32_t sB = sA + ABYTES;
        #pragma unroll
        for (int ks = 0; ks < 4; ks++) {
            uint32_t a[2][4];
            #pragma unroll
            for (int mi = 0; mi < 2; mi++) {
                uint32_t addr = sA +
                    (uint32_t)((wm * 32 + mi * 16 + (lane & 15)) * APAD + ks * 16 + 8 * (lane >> 4)) * 2;
                ldsm4(addr, a[mi][0], a[mi][1], a[mi][2], a[mi][3]);
            }
            #pragma unroll
            for (int ng = 0; ng < NT / 32; ng++) {
                uint32_t b0, b1, b2, b3;
                uint32_t addr = sB +
                    (uint32_t)((ks * 16 + (lane & 15)) * BPAD + wn * (NT / 2) + ng * 16 + 8 * (lane >> 4)) * 2;
                ldsm4t(addr, b0, b1, b2, b3);
                mma_bf16(acc[0][ng * 2],     a[0], b0, b1);
                mma_bf16(acc[0][ng * 2 + 1], a[0], b2, b3);
                mma_bf16(acc[1][ng * 2],     a[1], b0, b1);
                mma_bf16(acc[1][ng * 2 + 1], a[1], b2, b3);
            }
        }
    }

    // epilogue
    const int rb = row0 + wm * 32 + (lane >> 2);
    const int cb = wn * (NT / 2) + (lane & 3) * 2;
    #pragma unroll
    for (int mi = 0; mi < 2; mi++) {
        #pragma unroll
        for (int ni = 0; ni < NT / 16; ni++) {
            int col = cb + ni * 8;
            #pragma unroll
            for (int h = 0; h < 2; h++) {
                int rg = rb + mi * 16 + h * 8;
                if (rg < n) {
                    float2 v;
                    v.x = acc[mi][ni][h * 2 + 0];
                    v.y = acc[mi][ni][h * 2 + 1];
                    if (BIAS_RELU) {
                        v.x = fmaxf(v.x + bias[col], 0.f);
                        v.y = fmaxf(v.y + bias[col + 1], 0.f);
                    }
                    float* dst = out1;
                    int cc = col;
                    if (NT == 256 && col >= 128) { dst = out2; cc = col - 128; }
                    *(float2*)(dst + (size_t)rg * 128 + cc) = v;
                }
            }
        }
    }
}

// ---------------- CSR build ----------------
__global__ void k_zero(int n) {
    int i = blockIdx.x * blockDim.x + threadIdx.x;
    if (i < n) g_cnt[i] = 0;
}

__global__ void k_count(const int* __restrict__ dstv, int e) {
    int i = blockIdx.x * blockDim.x + threadIdx.x;
    if (i < e) atomicAdd(&g_cnt[dstv[i]], 1);
}

__global__ void k_scan_a(int n) {
    __shared__ int sh[256];
    int i = blockIdx.x * 256 + threadIdx.x;
    int v = (i < n) ? g_cnt[i] : 0;
    sh[threadIdx.x] = v;
    __syncthreads();
    #pragma unroll
    for (int o = 1; o < 256; o <<= 1) {
        int t = (threadIdx.x >= o) ? sh[threadIdx.x - o] : 0;
        __syncthreads();
        sh[threadIdx.x] += t;
        __syncthreads();
    }
    if (i < n) g_row[i] = sh[threadIdx.x] - v;
    if (threadIdx.x == 255) g_bsum[blockIdx.x] = sh[255];
}

__global__ void k_scan_b(int nb) {
    __shared__ int sh[NB_MAX];
    int t = threadIdx.x;
    int v = (t < nb) ? g_bsum[t] : 0;
    sh[t] = v;
    __syncthreads();
    #pragma unroll
    for (int o = 1; o < NB_MAX; o <<= 1) {
        int u = (t >= o) ? sh[t - o] : 0;
        __syncthreads();
        sh[t] += u;
        __syncthreads();
    }
    if (t < nb) g_bsum[t] = sh[t] - v;
}

__global__ void k_scan_c(int n, int e) {
    int i = blockIdx.x * 256 + threadIdx.x;
    if (i < n) {
        int r = g_row[i] + g_bsum[blockIdx.x];
        g_row[i] = r;
        g_cur[i] = r;
    }
    if (i == 0) g_row[n] = e;
}

__global__ void k_scatter(const int* __restrict__ srcv, const int* __restrict__ dstv, int e) {
    int i = blockIdx.x * blockDim.x + threadIdx.x;
    if (i < e) {
        int pos = atomicAdd(&g_cur[dstv[i]], 1);
        g_csrc[pos] = srcv[i];
    }
}

__global__ void k_sortcsr(int n) {
    int i = blockIdx.x * blockDim.x + threadIdx.x;
    if (i >= n) return;
    int b = g_row[i], e2 = g_row[i + 1];
    for (int a = b + 1; a < e2; a++) {
        int v = g_csrc[a];
        int k = a;
        while (k > b && g_csrc[k - 1] > v) { g_csrc[k] = g_csrc[k - 1]; k--; }
        g_csrc[k] = v;
    }
}

// ---------------- LayerNorm kernels (write bf16 hi/lo pack for the GEMM) ----------------
__global__ void __launch_bounds__(256) k_ln64(const float* __restrict__ x,
                                              const float* __restrict__ g,
                                              const float* __restrict__ b,
                                              __nv_bfloat16* __restrict__ pack, int n) {
    int w = (blockIdx.x * 256 + threadIdx.x) >> 5;
    int lane = threadIdx.x & 31;
    if (w >= n) return;
    float2 v = *(const float2*)(x + (size_t)w * 64 + lane * 2);
    float s = v.x + v.y;
    float q = v.x * v.x + v.y * v.y;
    #pragma unroll
    for (int o = 16; o; o >>= 1) {
        s += __shfl_xor_sync(0xffffffffu, s, o);
        q += __shfl_xor_sync(0xffffffffu, q, o);
    }
    float m  = s * (1.f / 64.f);
    float var = q * (1.f / 64.f) - m * m;
    float rs = rsqrtf(var + 1e-5f);
    float2 gg = *(const float2*)(g + lane * 2);
    float2 bb = *(const float2*)(b + lane * 2);
    float y0 = (v.x - m) * rs * gg.x + bb.x;
    float y1 = (v.y - m) * rs * gg.y + bb.y;
    __nv_bfloat16 h0 = __float2bfloat16(y0), h1 = __float2bfloat16(y1);
    __nv_bfloat16 l0 = __float2bfloat16(y0 - __bfloat162float(h0));
    __nv_bfloat16 l1 = __float2bfloat16(y1 - __bfloat162float(h1));
    uint32_t hw = ((uint32_t)__bfloat16_as_ushort(h1) << 16) | __bfloat16_as_ushort(h0);
    uint32_t lw = ((uint32_t)__bfloat16_as_ushort(l1) << 16) | __bfloat16_as_ushort(l0);
    *(uint32_t*)(pack + (size_t)w * 128 + lane * 2)      = hw;
    *(uint32_t*)(pack + (size_t)w * 128 + 64 + lane * 2) = lw;
}

__global__ void __launch_bounds__(256) k_ln128(const float* __restrict__ in,
                                               const float* __restrict__ g,
                                               const float* __restrict__ b,
                                               const float* __restrict__ res,
                                               float rscale, int doRelu,
                                               float* __restrict__ outf,
                                               __nv_bfloat16* __restrict__ pack, int n) {
    int w = (blockIdx.x * 256 + threadIdx.x) >> 5;
    int lane = threadIdx.x & 31;
    if (w >= n) return;
    int c0 = lane * 4;
    float4 v = *(const float4*)(in + (size_t)w * 128 + c0);
    float s = v.x + v.y + v.z + v.w;
    float q = v.x * v.x + v.y * v.y + v.z * v.z + v.w * v.w;
    #pragma unroll
    for (int o = 16; o; o >>= 1) {
        s += __shfl_xor_sync(0xffffffffu, s, o);
        q += __shfl_xor_sync(0xffffffffu, q, o);
    }
    float m   = s * (1.f / 128.f);
    float var = q * (1.f / 128.f) - m * m;
    float rs  = rsqrtf(var + 1e-5f);
    float4 gg = *(const float4*)(g + c0);
    float4 bb = *(const float4*)(b + c0);
    float4 y;
    y.x = (v.x - m) * rs * gg.x + bb.x;
    y.y = (v.y - m) * rs * gg.y + bb.y;
    y.z = (v.z - m) * rs * gg.z + bb.z;
    y.w = (v.w - m) * rs * gg.w + bb.w;
    if (res) {
        float4 r4 = *(const float4*)(res + (size_t)w * 128 + c0);
        y.x += rscale * r4.x; y.y += rscale * r4.y;
        y.z += rscale * r4.z; y.w += rscale * r4.w;
    }
    if (doRelu) {
        y.x = fmaxf(y.x, 0.f); y.y = fmaxf(y.y, 0.f);
        y.z = fmaxf(y.z, 0.f); y.w = fmaxf(y.w, 0.f);
    }
    if (outf) *(float4*)(outf + (size_t)w * 128 + c0) = y;
    uint2 hi, lo;
    split4(y, hi, lo);
    *(uint2*)(pack + (size_t)w * 256 + c0)       = hi;
    *(uint2*)(pack + (size_t)w * 256 + 128 + c0) = lo;
}

// ---------------- GATv2 aggregation: warp per dst node, online softmax ----------------
__global__ void __launch_bounds__(256) k_agg(const float* __restrict__ xl,
                                             const float* __restrict__ xr,
                                             const float* __restrict__ att,
                                             float* __restrict__ out, int n, int grp) {
    int w = (blockIdx.x * 256 + threadIdx.x) >> 5;
    int lane = threadIdx.x & 31;
    if (w >= n) return;
    int c0 = lane * 4;
    float4 a4 = *(const float4*)(att + c0);
    float4 r4 = *(const float4*)(xr + (size_t)w * 128 + c0);
    int beg = g_row[w], deg = g_row[w + 1] - beg;
    float m = -1e30f, s = 0.f;
    float4 acc = make_float4(0.f, 0.f, 0.f, 0.f);
    for (int j = -1; j < deg; j++) {       // j == -1 is the self-loop
        int sidx = (j < 0) ? w : g_csrc[beg + j];
        float4 x4 = *(const float4*)(xl + (size_t)sidx * 128 + c0);
        float e0 = x4.x + r4.x, e1 = x4.y + r4.y, e2 = x4.z + r4.z, e3 = x4.w + r4.w;
        e0 = (e0 > 0.f) ? e0 : 0.2f * e0;
        e1 = (e1 > 0.f) ? e1 : 0.2f * e1;
        e2 = (e2 > 0.f) ? e2 : 0.2f * e2;
        e3 = (e3 > 0.f) ? e3 : 0.2f * e3;
        float p = fmaf(a4.x, e0, fmaf(a4.y, e1, fmaf(a4.z, e2, a4.w * e3)));
        #pragma unroll
        for (int o = 1; o < 32; o <<= 1)
            if (o < grp) p += __shfl_xor_sync(0xffffffffu, p, o);
        float mn  = fmaxf(m, p);
        float sc  = __expf(m - mn);
        float wgt = __expf(p - mn);
        s = s * sc + wgt;
        acc.x = fmaf(acc.x, sc, wgt * x4.x);
        acc.y = fmaf(acc.y, sc, wgt * x4.y);
        acc.z = fmaf(acc.z, sc, wgt * x4.z);
        acc.w = fmaf(acc.w, sc, wgt * x4.w);
        m = mn;
    }
    float inv = 1.f / s;
    float4 o4 = make_float4(acc.x * inv, acc.y * inv, acc.z * inv, acc.w * inv);
    *(float4*)(out + (size_t)w * 128 + c0) = o4;
}

// ---------------- prediction heads ----------------
__global__ void __launch_bounds__(256) k_head2(const float* __restrict__ T,
                                               const float* __restrict__ w2a,
                                               const float* __restrict__ b2a,
                                               const float* __restrict__ w2b,
                                               const float* __restrict__ b2b,
                                               float* __restrict__ out, int n) {
    int w = (blockIdx.x * 256 + threadIdx.x) >> 5;
    int lane = threadIdx.x & 31;
    if (w >= n) return;
    const float* t = T + (size_t)w * 128;
    float tA = fmaf(t[lane],      w2a[lane],      t[32 + lane] * w2a[32 + lane]);
    float tB = fmaf(t[64 + lane], w2b[lane],      t[96 + lane] * w2b[32 + lane]);
    #pragma unroll
    for (int o = 16; o; o >>= 1) {
        tA += __shfl_xor_sync(0xffffffffu, tA, o);
        tB += __shfl_xor_sync(0xffffffffu, tB, o);
    }
    if (lane == 0) {
        out[(size_t)2 * w]     = tA + b2a[0];
        out[(size_t)2 * w + 1] = tB + b2b[0];
    }
}

// ---------------- launch ----------------
extern "C" void kernel_launch(void* const* d_in, const int* in_sizes, int n_in,
                              void* d_out, int out_size) {
    const float* x       = (const float*)d_in[0];
    const int*   ei      = (const int*)  d_in[1];
    const float* ln_in_g = (const float*)d_in[2];
    const float* ln_in_b = (const float*)d_in[3];
    const float* w_l1    = (const float*)d_in[4];
    const float* w_r1    = (const float*)d_in[5];
    const float* att1    = (const float*)d_in[6];
    const float* ln1_g   = (const float*)d_in[7];
    const float* ln1_b   = (const float*)d_in[8];
    const float* w_l2    = (const float*)d_in[9];
    const float* w_r2    = (const float*)d_in[10];
    const float* att2    = (const float*)d_in[11];
    const float* ln2_g   = (const float*)d_in[12];
    const float* ln2_b   = (const float*)d_in[13];
    const float* w_l3    = (const float*)d_in[14];
    const float* w_r3    = (const float*)d_in[15];
    const float* att3    = (const float*)d_in[16];
    const float* ln3_g   = (const float*)d_in[17];
    const float* ln3_b   = (const float*)d_in[18];
    const float* rtt_w1  = (const float*)d_in[19];
    const float* rtt_b1  = (const float*)d_in[20];
    const float* rtt_w2  = (const float*)d_in[21];
    const float* rtt_b2  = (const float*)d_in[22];
    const float* ret_w1  = (const float*)d_in[23];
    const float* ret_b1  = (const float*)d_in[24];
    const float* ret_w2  = (const float*)d_in[25];
    const float* ret_b2  = (const float*)d_in[26];

    const int n = in_sizes[0] / 64;
    const int e = in_sizes[1] / 2;
    const int* srcv = ei;
    const int* dstv = ei + e;

    float *p_h, *p_xl, *p_xr, *p_gg, *p_b1;
    __nv_bfloat16 *p_pk, *p_W0, *p_W1, *p_W2, *p_WH;
    cudaGetSymbolAddress((void**)&p_h,  g_h);
    cudaGetSymbolAddress((void**)&p_xl, g_xl);
    cudaGetSymbolAddress((void**)&p_xr, g_xr);
    cudaGetSymbolAddress((void**)&p_gg, g_gg);
    cudaGetSymbolAddress((void**)&p_b1, g_b1cat);
    cudaGetSymbolAddress((void**)&p_pk, g_pk);
    cudaGetSymbolAddress((void**)&p_W0, g_W0);
    cudaGetSymbolAddress((void**)&p_W1, g_W1);
    cudaGetSymbolAddress((void**)&p_W2, g_W2);
    cudaGetSymbolAddress((void**)&p_WH, g_WH);

    const int NBn = (n + 255) / 256;
    const int EB  = (e + 255) / 256;
    const int WB  = (n + 7) / 8;       // warp-per-node, 256-thread blocks
    const int GB  = (n + 127) / 128;   // GEMM M-tiles

    // dynamic smem for GEMM (3 stages)
    const int STG256 = 128 * APAD * 2 + 64 * (256 + 8) * 2;   // 18432 + 33792
    const int STG128 = 128 * APAD * 2 + 64 * (128 + 8) * 2;   // 18432 + 17408
    const int SM256 = 3 * STG256;                              // 156672
    const int SM128 = 3 * STG128;                              // 107520
    cudaFuncSetAttribute((const void*)k_gemm_mma<64, 256, false>,
                         cudaFuncAttributeMaxDynamicSharedMemorySize, SM256);
    cudaFuncSetAttribute((const void*)k_gemm_mma<128, 256, false>,
                         cudaFuncAttributeMaxDynamicSharedMemorySize, SM256);
    cudaFuncSetAttribute((const void*)k_gemm_mma<128, 128, true>,
                         cudaFuncAttributeMaxDynamicSharedMemorySize, SM128);

    // CSR build (shared by all three layers)
    k_zero   <<<NBn, 256>>>(n);
    k_count  <<<EB,  256>>>(dstv, e);
    k_scan_a <<<NBn, 256>>>(n);
    k_scan_b <<<1, NB_MAX>>>(NBn);
    k_scan_c <<<NBn, 256>>>(n, e);
    k_scatter<<<EB,  256>>>(srcv, dstv, e);
    k_sortcsr<<<NBn, 256>>>(n);

    // weight image pre-conversion (tiny)
    k_convW<64, 256> <<<(3 * 64 * 256 + 255) / 256, 256>>>(w_l1, w_r1, p_W0);
    k_convW<128, 256><<<(3 * 128 * 256 + 255) / 256, 256>>>(w_l2, w_r2, p_W1);
    k_convW<128, 256><<<(3 * 128 * 256 + 255) / 256, 256>>>(w_l3, w_r3, p_W2);
    k_convW<128, 128><<<(3 * 128 * 128 + 255) / 256, 256>>>(rtt_w1, ret_w1, p_WH);
    k_biascat<<<1, 128>>>(rtt_b1, ret_b1);

    // input LayerNorm: x -> bf16 pack [n, 128]
    k_ln64<<<WB, 256>>>(x, ln_in_g, ln_in_b, p_pk, n);

    // layer 0 (F_IN=64 -> 128, 4 heads, no residual)
    k_gemm_mma<64, 256, false><<<GB, 256, SM256>>>(p_pk, p_W0, p_xl, p_xr, nullptr, n);
    k_agg<<<WB, 256>>>(p_xl, p_xr, att1, p_gg, n, 8);
    k_ln128<<<WB, 256>>>(p_gg, ln1_g, ln1_b, nullptr, 0.f, 1, p_h, p_pk, n);

    // layer 1 (128 -> 128, 4 heads, residual*0.1, relu)
    k_gemm_mma<128, 256, false><<<GB, 256, SM256>>>(p_pk, p_W1, p_xl, p_xr, nullptr, n);
    k_agg<<<WB, 256>>>(p_xl, p_xr, att2, p_gg, n, 8);
    k_ln128<<<WB, 256>>>(p_gg, ln2_g, ln2_b, p_h, 0.1f, 1, p_h, p_pk, n);

    // layer 2 (128 -> 128, 1 head, residual*0.1, no relu)
    k_gemm_mma<128, 256, false><<<GB, 256, SM256>>>(p_pk, p_W2, p_xl, p_xr, nullptr, n);
    k_agg<<<WB, 256>>>(p_xl, p_xr, att3, p_gg, n, 32);
    k_ln128<<<WB, 256>>>(p_gg, ln3_g, ln3_b, p_h, 0.1f, 0, nullptr, p_pk, n);

    // prediction heads: T = relu(h @ [rtt_w1|ret_w1] + b) ; out = heads(T)
    k_gemm_mma<128, 128, true><<<GB, 256, SM128>>>(p_pk, p_WH, p_xl, nullptr, p_b1, n);
    k_head2<<<WB, 256>>>(p_xl, rtt_w2, rtt_b2, ret_w2, ret_b2, (float*)d_out, n);
}